// round 16
// baseline (speedup 1.0000x reference)
#include <cuda_runtime.h>
#include <cuda_fp16.h>
#include <math.h>

#define HH 512
#define WW 512
#define AA 180
#define TST 516             // pair-image row stride in half2 (2064 B/row)
#define ROWB (TST * 4)      // tile row stride in bytes
#define CH 16               // padded top-rows per chunk
#define NCHUNK 33           // ceil(513 / 16)
#define NSPLIT 10           // chunk-groups per angle -> 1800 blocks
#define TILE_H2 (CH * TST)  // 8256 half2 = 33,024 B per buffer
#define DYN_SMEM (2 * TILE_H2 * 4)   // 66,048 B -> 3 blocks/SM

#define NORM_BLKS 513
#define TRANS_BLKS 289      // 17 x 17
#define TV_BLKS 64
#define PREP_BLKS (NORM_BLKS + TRANS_BLKS + TV_BLKS)   // 866

// Vertical-pair images: g_V[y*TST+s] = half2(P(y,s-1), P(y+1,s-1)),
// P(r,c) = pred[r-1][c-1] inside [1,512]^2 else 0. Cols s=0,1,514,515 are zero.
__device__ __align__(16) __half2 g_V[513 * TST];
__device__ __align__(16) __half2 g_VT[513 * TST];   // transposed orientation
__device__ __align__(16) float g_sino[AA * WW];
__device__ double g_tvpart[TV_BLKS];   // TV partials (deterministic slots)
__device__ double g_acc0;              // MSE accumulator
__device__ unsigned g_acnt[AA];        // per-angle completion counters
__device__ unsigned g_done;            // angle-MSE completion counter

// ---------------- cp.async helpers ----------------
__device__ __forceinline__ void cp_async16(void* smem, const void* gmem) {
    unsigned s = (unsigned)__cvta_generic_to_shared(smem);
    asm volatile("cp.async.cg.shared.global [%0], [%1], 16;\n" :: "r"(s), "l"(gmem));
}
__device__ __forceinline__ void cp_commit() {
    asm volatile("cp.async.commit_group;\n");
}
template <int N> __device__ __forceinline__ void cp_wait() {
    asm volatile("cp.async.wait_group %0;\n" :: "n"(N));
}

// ---------------------------------------------------------------------------
// Kernel 1 (fused prep): role by blockIdx.x.
//   [0,513):    normal vertical-pair rows + zero sino/counters
//   [513,802):  transposed vertical-pair tiles (all 17 warps)
//   [802,866):  TV partial sums -> g_tvpart slots
// ---------------------------------------------------------------------------
__global__ __launch_bounds__(544) void prep_kernel(const float* __restrict__ pred) {
    const int role = blockIdx.x;
    const int tid  = threadIdx.x;

    if (role < NORM_BLKS) {
        const int y = role;            // 0..512
        if (tid < TST) {
            float a = 0.0f, b = 0.0f;
            if (tid >= 2 && tid <= 513) {
                const int pc = tid - 2;
                if (y >= 1 && y <= 512) a = pred[(y - 1) * 512 + pc];
                if (y <= 511)           b = pred[y * 512 + pc];
            }
            g_V[y * TST + tid] = __floats2half2_rn(a, b);
        }
        const int gid = role * 544 + tid;
        if (gid < AA * WW) g_sino[gid] = 0.0f;
        if (gid < AA) g_acnt[gid] = 0u;
        if (gid == 0) { g_acc0 = 0.0; g_done = 0u; }

    } else if (role < NORM_BLKS + TRANS_BLKS) {
        __shared__ float t[32][35];
        const int idx = role - NORM_BLKS;
        const int s0 = (idx % 17) * 32;
        const int y0 = (idx / 17) * 32;
        const int tx = tid & 31;
        const int ty = tid >> 5;       // 0..16 — all warps participate

        for (int i = ty; i < 32; i += 17) {
            const int pr = s0 - 2 + i;
            {
                const int pc = y0 - 1 + tx;
                t[i][tx] = ((unsigned)pr < 512u && (unsigned)pc < 512u)
                           ? pred[pr * 512 + pc] : 0.0f;
            }
            if (tx < 2) {
                const int pc = y0 + 31 + tx;
                t[i][32 + tx] = ((unsigned)pr < 512u && (unsigned)pc < 512u)
                                ? pred[pr * 512 + pc] : 0.0f;
            }
        }
        __syncthreads();
        for (int j = ty; j < 32; j += 17) {
            const int y = y0 + j;
            const int s = s0 + tx;
            if (y < 513 && s < TST)
                g_VT[y * TST + s] = __floats2half2_rn(t[tx][j], t[tx][j + 1]);
        }

    } else {
        // TV partials: 511 rows x 128 float4 groups = 65408 items.
        const int slot = role - NORM_BLKS - TRANS_BLKS;          // 0..63
        const int gtid = slot * 544 + tid;
        const int gstr = TV_BLKS * 544;
        float lt = 0.0f;
        for (int it = gtid; it < 511 * 128; it += gstr) {
            const int y = it >> 7;
            const int x = (it & 127) << 2;
            const float4 p = *(const float4*)(pred + y * 512 + x);
            const float4 q = *(const float4*)(pred + (y + 1) * 512 + x);
            const float dy0 = q.x - p.x, dy1 = q.y - p.y;
            const float dy2 = q.z - p.z, dy3 = q.w - p.w;
            const float dx0 = p.y - p.x, dx1 = p.z - p.y, dx2 = p.w - p.z;
            lt += sqrtf(fmaf(dx0, dx0, fmaf(dy0, dy0, 1e-8f)));
            lt += sqrtf(fmaf(dx1, dx1, fmaf(dy1, dy1, 1e-8f)));
            lt += sqrtf(fmaf(dx2, dx2, fmaf(dy2, dy2, 1e-8f)));
            if (x < 508) {
                const float p4  = pred[y * 512 + x + 4];
                const float dx3 = p4 - p.w;
                lt += sqrtf(fmaf(dx3, dx3, fmaf(dy3, dy3, 1e-8f)));
            }
        }
        for (int off = 16; off > 0; off >>= 1)
            lt += __shfl_down_sync(0xFFFFFFFFu, lt, off);
        __shared__ float s_lt[17];
        if ((tid & 31) == 0) s_lt[tid >> 5] = lt;
        __syncthreads();
        if (tid == 0) {
            float tot = 0.0f;
            for (int i = 0; i < 17; i++) tot += s_lt[i];
            g_tvpart[slot] = (double)tot;
        }
    }
}

// ---------------------------------------------------------------------------
// Exact first-j with iy(j) >= bound (ceilf estimate corrected +-1 against the
// same fmaf formula -> adjacent chunks compute bitwise-identical boundaries).
// ---------------------------------------------------------------------------
__device__ __forceinline__ int first_j_ge(float bound, float iyS, float cy, float invcy) {
    int j = (int)ceilf((bound - iyS) * invcy);
    if (fmaf((float)(j - 1), cy, iyS) >= bound) j -= 1;
    if (fmaf((float)j, cy, iyS) < bound)        j += 1;
    return j;
}

// ---------------------------------------------------------------------------
// Incremental DDA chunk accumulation (XPOS = x-step sign variant).
// ---------------------------------------------------------------------------
template <bool XPOS>
__device__ __forceinline__ float chunk_accum(const __half2* __restrict__ tb,
                                             int len, int nr,
                                             float iyl0, float ix0,
                                             float cy, float dxj) {
    int yi0 = __float2int_rd(iyl0);
    yi0 = min(max(yi0, 0), nr - 1);
    float wy = iyl0 - (float)yi0;
    int rowoff = yi0 * ROWB;
    const unsigned rowcap = (unsigned)((nr - 1) * ROWB);

    int si = __float2int_rd(ix0);
    float wx = ix0 - (float)si;

    const char* __restrict__ base = (const char*)tb;
    float acc = 0.0f;

    #pragma unroll 4
    for (int k = 0; k < len; k++) {
        const unsigned sic = min((unsigned)si, 514u);
        const unsigned roc = min((unsigned)rowoff, rowcap);
        const __half2* p = (const __half2*)(base + roc + sic * 4u);
        const __half2 A = p[0];                    // (v00, v10)
        const __half2 B = p[1];                    // (v01, v11)
        const __half2 wxy = __floats2half2_rn(wx, wy);          // 1 F2FP
        const __half2 wx2 = __half2half2(__low2half(wxy));      // PRMT
        const __half2 wy2 = __half2half2(__high2half(wxy));     // PRMT
        const __half2 mm  = __hfma2(wx2, __hsub2(B, A), A);     // (top, bot)
        const __half2 sw  = __lowhigh2highlow(mm);              // (bot, top)
        const __half2 res = __hfma2(wy2, __hsub2(sw, mm), mm);  // lo = bilinear
        acc += __low2float(res);                   // 1 F2F

        wy += cy;
        {
            const bool oy = (wy >= 1.0f);
            wy     = oy ? wy - 1.0f     : wy;
            rowoff = oy ? rowoff + ROWB : rowoff;
        }
        wx += dxj;
        if (XPOS) {
            const bool ox = (wx >= 1.0f);
            wx = ox ? wx - 1.0f : wx;
            si = ox ? si + 1    : si;
        } else {
            const bool ox = (wx < 0.0f);
            wx = ox ? wx + 1.0f : wx;
            si = ox ? si - 1    : si;
        }
    }
    return acc;
}

// ---------------------------------------------------------------------------
// Kernel 2: radon + per-angle MSE tail + finalize (last angle writes out).
// ---------------------------------------------------------------------------
__global__ __launch_bounds__(512, 3) void radon_kernel(const float* __restrict__ angles,
                                                       const float* __restrict__ sino_tgt,
                                                       float* __restrict__ out) {
    extern __shared__ __align__(16) unsigned char dynsmem[];
    __half2* const tbuf0 = (__half2*)dynsmem;
    __half2* const tbuf1 = tbuf0 + TILE_H2;

    const int a = blockIdx.x;
    const int w = threadIdx.x;

    const float ang = angles[a];
    const float sn = sinf(ang);
    const float cs = cosf(ang);
    const bool  swp = fabsf(sn) > fabsf(cs);

    const float c = swp ? -sn : cs;                    // |c| >= 0.7071
    const float d = swp ?  cs : -sn;
    const float u = (float)w + 0.5f - 256.0f;
    const float by = fmaf(swp ? cs : sn, u, 255.5f);
    const float bx = fmaf(swp ? sn : cs, u, 255.5f);
    const __half2* __restrict__ img = swp ? g_VT : g_V;

    const float sgn   = (c >= 0.0f) ? 1.0f : -1.0f;
    const float cy    = fabsf(c);
    const float invcy = 1.0f / cy;
    const float iyS   = fmaf(-255.5f, cy, by);         // iy at j=0, increasing
    const float dxj   = sgn * d;
    const float ixS   = fmaf(-sgn * 255.5f, d, bx);
    const bool  xpos  = (dxj >= 0.0f);                 // block-uniform

    // Per-thread x-window (skips only provably-zero samples).
    int jx0 = 0, jx1 = 512;
    {
        const float ad = fabsf(dxj);
        if (ad > 1e-9f) {
            const float t0 = (-1.5f  - ixS) / dxj;
            const float t1 = (512.5f - ixS) / dxj;
            const float lo = fminf(t0, t1);
            const float hi = fmaxf(t0, t1);
            jx0 = max(0,   (int)floorf(lo) - 1);
            jx1 = min(512, (int)ceilf(hi) + 2);
        } else if (ixS < -1.5f || ixS > 512.5f) {
            jx0 = 0; jx1 = 0;
        }
    }

    const int c0 = (NCHUNK * blockIdx.y) / NSPLIT;
    const int c1 = (NCHUNK * (blockIdx.y + 1)) / NSPLIT;

    auto stage = [&](int m, __half2* dstbuf) {
        const int R  = m * CH;
        const int nr = min(R + CH, 513) - R;
        const int n16 = nr * (TST / 4);
        const float4* __restrict__ src = (const float4*)(img + R * TST);
        float4* dst = (float4*)dstbuf;
        for (int t = threadIdx.x; t < n16; t += 512)
            cp_async16(&dst[t], &src[t]);
        cp_commit();
    };

    stage(c0, (c0 & 1) ? tbuf1 : tbuf0);

    float acc = 0.0f;

    for (int m = c0; m < c1; m++) {
        if (m + 1 < c1) {
            stage(m + 1, ((m + 1) & 1) ? tbuf1 : tbuf0);
            cp_wait<1>();
        } else {
            cp_wait<0>();
        }
        __syncthreads();

        const int R  = m * CH;
        const int nr = min(R + CH, 513) - R;

        int jlo = first_j_ge((float)(R - 1),      iyS, cy, invcy);
        int jhi = first_j_ge((float)(R + nr - 1), iyS, cy, invcy);
        jlo = max(max(jlo, 0),   jx0);
        jhi = min(min(jhi, 512), jx1);
        const int len = jhi - jlo;

        const float iyl0 = fmaf((float)jlo, cy,  iyS) - (float)(R - 1);
        const float ix0  = fmaf((float)jlo, dxj, ixS) + 2.0f;

        const __half2* __restrict__ tb = (m & 1) ? tbuf1 : tbuf0;

        if (xpos) acc += chunk_accum<true >(tb, len, nr, iyl0, ix0, cy, dxj);
        else      acc += chunk_accum<false>(tb, len, nr, iyl0, ix0, cy, dxj);

        __syncthreads();
    }

    atomicAdd(&g_sino[a * WW + w], acc);
    __threadfence();                    // my sino atomic visible before counter
    __syncthreads();                    // all threads fenced

    __shared__ int s_last, s_fin;
    if (w == 0) {
        const unsigned done = atomicAdd(&g_acnt[a], 1u);
        s_last = (done == NSPLIT - 1) ? 1 : 0;
    }
    __syncthreads();

    if (s_last) {
        // This block is the 10th (last) for angle a: all contributions visible.
        const float df = g_sino[a * WW + w] - sino_tgt[a * WW + w];
        float lp = df * df;
        for (int off = 16; off > 0; off >>= 1)
            lp += __shfl_down_sync(0xFFFFFFFFu, lp, off);
        __shared__ float s_lp[16];
        const int lane = w & 31;
        const int warp = w >> 5;
        if (lane == 0) s_lp[warp] = lp;
        __syncthreads();
        if (w == 0) {
            float tot = 0.0f;
            for (int i = 0; i < 16; i++) tot += s_lp[i];
            atomicAdd(&g_acc0, (double)tot);
            __threadfence();
            const unsigned dd = atomicAdd(&g_done, 1u);
            s_fin = (dd == AA - 1) ? 1 : 0;
        }
        __syncthreads();

        if (s_fin) {
            // Final angle: finalize. TV partials from prep (kernel-boundary
            // visible); g_acc0 complete (all 180 fenced adds observed).
            double v = (w < TV_BLKS) ? g_tvpart[w] : 0.0;
            for (int off = 16; off > 0; off >>= 1)
                v += __shfl_down_sync(0xFFFFFFFFu, v, off);
            __shared__ double s_d[16];
            if (lane == 0) s_d[warp] = v;
            __syncthreads();
            if (w == 0) {
                double tv = 0.0;
                for (int i = 0; i < 2; i++) tv += s_d[i];   // TV_BLKS=64 -> warps 0,1
                __threadfence();
                const double loss_proj = g_acc0 / (double)(AA * WW);
                const double loss_tv   = tv / (double)((HH - 1) * (WW - 1));
                out[0] = (float)(loss_proj + 0.01 * loss_tv);
            }
        }
    }
}

// ---------------------------------------------------------------------------
extern "C" void kernel_launch(void* const* d_in, const int* in_sizes, int n_in,
                              void* d_out, int out_size) {
    const float* pred     = (const float*)d_in[0];   // [1,512,512]
    const float* sinogram = (const float*)d_in[1];   // [1,180,512]
    const float* angles   = (const float*)d_in[2];   // [180]
    float* out = (float*)d_out;

    cudaFuncSetAttribute(radon_kernel,
                         cudaFuncAttributeMaxDynamicSharedMemorySize, DYN_SMEM);

    prep_kernel<<<PREP_BLKS, 544>>>(pred);

    dim3 rgrid(AA, NSPLIT);                          // 180 x 10 = 1800 blocks
    radon_kernel<<<rgrid, 512, DYN_SMEM>>>(angles, sinogram, out);
}

// round 17
// speedup vs baseline: 1.1494x; 1.1494x over previous
#include <cuda_runtime.h>
#include <cuda_fp16.h>
#include <math.h>

#define HH 512
#define WW 512
#define AA 180
#define TST 516             // pair-image row stride in half2 (2064 B/row)
#define ROWB (TST * 4)      // tile row stride in bytes
#define CH 18               // padded top-rows per chunk
#define NCHUNK 29           // ceil(513 / 18)
#define NSPLIT 10           // chunk-groups per angle -> 1800 blocks
#define TILE_H2 (CH * TST)  // 9288 half2 = 37,152 B per buffer
#define DYN_SMEM (2 * TILE_H2 * 4)   // 74,304 B -> 3 blocks/SM = 222.9 KB

#define NORM_BLKS 513
#define TRANS_BLKS 289      // 17 x 17
#define TV_BLKS 64
#define PREP_BLKS (NORM_BLKS + TRANS_BLKS + TV_BLKS)   // 866
#define MSE_BLKS 90         // 90 x 256 = 23040 threads = one float4 each

// Vertical-pair images: g_V[y*TST+s] = half2(P(y,s-1), P(y+1,s-1)),
// P(r,c) = pred[r-1][c-1] inside [1,512]^2 else 0. Cols s=0,1,514,515 are zero.
__device__ __align__(16) __half2 g_V[513 * TST];
__device__ __align__(16) __half2 g_VT[513 * TST];   // transposed orientation
__device__ __align__(16) float g_sino[AA * WW];
__device__ double g_tvpart[TV_BLKS];   // TV partials (deterministic slots)
__device__ double g_acc0;              // MSE accumulator
__device__ unsigned g_cnt;             // MSE-block completion counter

// ---------------- cp.async helpers ----------------
__device__ __forceinline__ void cp_async16(void* smem, const void* gmem) {
    unsigned s = (unsigned)__cvta_generic_to_shared(smem);
    asm volatile("cp.async.cg.shared.global [%0], [%1], 16;\n" :: "r"(s), "l"(gmem));
}
__device__ __forceinline__ void cp_commit() {
    asm volatile("cp.async.commit_group;\n");
}
template <int N> __device__ __forceinline__ void cp_wait() {
    asm volatile("cp.async.wait_group %0;\n" :: "n"(N));
}

// ---------------------------------------------------------------------------
// Kernel 1 (fused prep): role by blockIdx.x.
//   [0,513):    normal vertical-pair rows + zero sino/accumulators
//   [513,802):  transposed vertical-pair tiles (all 17 warps)
//   [802,866):  TV partial sums -> g_tvpart slots (no atomics)
// ---------------------------------------------------------------------------
__global__ __launch_bounds__(544) void prep_kernel(const float* __restrict__ pred) {
    const int role = blockIdx.x;
    const int tid  = threadIdx.x;

    if (role < NORM_BLKS) {
        const int y = role;            // 0..512
        if (tid < TST) {
            float a = 0.0f, b = 0.0f;
            if (tid >= 2 && tid <= 513) {
                const int pc = tid - 2;
                if (y >= 1 && y <= 512) a = pred[(y - 1) * 512 + pc];
                if (y <= 511)           b = pred[y * 512 + pc];
            }
            g_V[y * TST + tid] = __floats2half2_rn(a, b);
        }
        const int gid = role * 544 + tid;
        if (gid < AA * WW) g_sino[gid] = 0.0f;
        if (gid == 0) { g_acc0 = 0.0; g_cnt = 0u; }

    } else if (role < NORM_BLKS + TRANS_BLKS) {
        __shared__ float t[32][35];
        const int idx = role - NORM_BLKS;
        const int s0 = (idx % 17) * 32;
        const int y0 = (idx / 17) * 32;
        const int tx = tid & 31;
        const int ty = tid >> 5;       // 0..16 — all warps participate

        for (int i = ty; i < 32; i += 17) {
            const int pr = s0 - 2 + i;
            {
                const int pc = y0 - 1 + tx;
                t[i][tx] = ((unsigned)pr < 512u && (unsigned)pc < 512u)
                           ? pred[pr * 512 + pc] : 0.0f;
            }
            if (tx < 2) {
                const int pc = y0 + 31 + tx;
                t[i][32 + tx] = ((unsigned)pr < 512u && (unsigned)pc < 512u)
                                ? pred[pr * 512 + pc] : 0.0f;
            }
        }
        __syncthreads();
        for (int j = ty; j < 32; j += 17) {
            const int y = y0 + j;
            const int s = s0 + tx;
            if (y < 513 && s < TST)
                g_VT[y * TST + s] = __floats2half2_rn(t[tx][j], t[tx][j + 1]);
        }

    } else {
        // TV partials: 511 rows x 128 float4 groups = 65408 items.
        const int slot = role - NORM_BLKS - TRANS_BLKS;          // 0..63
        const int gtid = slot * 544 + tid;
        const int gstr = TV_BLKS * 544;
        float lt = 0.0f;
        for (int it = gtid; it < 511 * 128; it += gstr) {
            const int y = it >> 7;
            const int x = (it & 127) << 2;
            const float4 p = *(const float4*)(pred + y * 512 + x);
            const float4 q = *(const float4*)(pred + (y + 1) * 512 + x);
            const float dy0 = q.x - p.x, dy1 = q.y - p.y;
            const float dy2 = q.z - p.z, dy3 = q.w - p.w;
            const float dx0 = p.y - p.x, dx1 = p.z - p.y, dx2 = p.w - p.z;
            lt += sqrtf(fmaf(dx0, dx0, fmaf(dy0, dy0, 1e-8f)));
            lt += sqrtf(fmaf(dx1, dx1, fmaf(dy1, dy1, 1e-8f)));
            lt += sqrtf(fmaf(dx2, dx2, fmaf(dy2, dy2, 1e-8f)));
            if (x < 508) {
                const float p4  = pred[y * 512 + x + 4];
                const float dx3 = p4 - p.w;
                lt += sqrtf(fmaf(dx3, dx3, fmaf(dy3, dy3, 1e-8f)));
            }
        }
        for (int off = 16; off > 0; off >>= 1)
            lt += __shfl_down_sync(0xFFFFFFFFu, lt, off);
        __shared__ float s_lt[17];
        if ((tid & 31) == 0) s_lt[tid >> 5] = lt;
        __syncthreads();
        if (tid == 0) {
            float tot = 0.0f;
            for (int i = 0; i < 17; i++) tot += s_lt[i];
            g_tvpart[slot] = (double)tot;
        }
    }
}

// ---------------------------------------------------------------------------
// Exact first-j with iy(j) >= bound (ceilf estimate corrected +-1 against the
// same fmaf formula -> adjacent chunks compute bitwise-identical boundaries).
// ---------------------------------------------------------------------------
__device__ __forceinline__ int first_j_ge(float bound, float iyS, float cy, float invcy) {
    int j = (int)ceilf((bound - iyS) * invcy);
    if (fmaf((float)(j - 1), cy, iyS) >= bound) j -= 1;
    if (fmaf((float)j, cy, iyS) < bound)        j += 1;
    return j;
}

// ---------------------------------------------------------------------------
// Incremental DDA chunk accumulation (XPOS = x-step sign variant).
// ---------------------------------------------------------------------------
template <bool XPOS>
__device__ __forceinline__ float chunk_accum(const __half2* __restrict__ tb,
                                             int len, int nr,
                                             float iyl0, float ix0,
                                             float cy, float dxj) {
    int yi0 = __float2int_rd(iyl0);
    yi0 = min(max(yi0, 0), nr - 1);
    float wy = iyl0 - (float)yi0;
    int rowoff = yi0 * ROWB;
    const unsigned rowcap = (unsigned)((nr - 1) * ROWB);

    int si = __float2int_rd(ix0);
    float wx = ix0 - (float)si;

    const char* __restrict__ base = (const char*)tb;
    float acc = 0.0f;

    #pragma unroll 4
    for (int k = 0; k < len; k++) {
        const unsigned sic = min((unsigned)si, 514u);
        const unsigned roc = min((unsigned)rowoff, rowcap);
        const __half2* p = (const __half2*)(base + roc + sic * 4u);
        const __half2 A = p[0];                    // (v00, v10)
        const __half2 B = p[1];                    // (v01, v11)
        const __half2 wxy = __floats2half2_rn(wx, wy);          // 1 F2FP
        const __half2 wx2 = __half2half2(__low2half(wxy));
        const __half2 wy2 = __half2half2(__high2half(wxy));
        const __half2 mm  = __hfma2(wx2, __hsub2(B, A), A);     // (top, bot)
        const __half2 sw  = __lowhigh2highlow(mm);              // (bot, top)
        const __half2 res = __hfma2(wy2, __hsub2(sw, mm), mm);  // lo = bilinear
        acc += __low2float(res);                   // 1 F2F

        wy += cy;
        {
            const bool oy = (wy >= 1.0f);
            wy     = oy ? wy - 1.0f     : wy;
            rowoff = oy ? rowoff + ROWB : rowoff;
        }
        wx += dxj;
        if (XPOS) {
            const bool ox = (wx >= 1.0f);
            wx = ox ? wx - 1.0f : wx;
            si = ox ? si + 1    : si;
        } else {
            const bool ox = (wx < 0.0f);
            wx = ox ? wx + 1.0f : wx;
            si = ox ? si - 1    : si;
        }
    }
    return acc;
}

// ---------------------------------------------------------------------------
// Kernel 2: radon, exact j-windows + x-clip, CH=18 double buffer.
// ---------------------------------------------------------------------------
__global__ __launch_bounds__(512, 3) void radon_kernel(const float* __restrict__ angles) {
    extern __shared__ __align__(16) unsigned char dynsmem[];
    __half2* const tbuf0 = (__half2*)dynsmem;
    __half2* const tbuf1 = tbuf0 + TILE_H2;

    const int a = blockIdx.x;
    const int w = threadIdx.x;

    const float ang = angles[a];
    const float sn = sinf(ang);
    const float cs = cosf(ang);
    const bool  swp = fabsf(sn) > fabsf(cs);

    const float c = swp ? -sn : cs;                    // |c| >= 0.7071
    const float d = swp ?  cs : -sn;
    const float u = (float)w + 0.5f - 256.0f;
    const float by = fmaf(swp ? cs : sn, u, 255.5f);
    const float bx = fmaf(swp ? sn : cs, u, 255.5f);
    const __half2* __restrict__ img = swp ? g_VT : g_V;

    const float sgn   = (c >= 0.0f) ? 1.0f : -1.0f;
    const float cy    = fabsf(c);
    const float invcy = 1.0f / cy;
    const float iyS   = fmaf(-255.5f, cy, by);         // iy at j=0, increasing
    const float dxj   = sgn * d;
    const float ixS   = fmaf(-sgn * 255.5f, d, bx);
    const bool  xpos  = (dxj >= 0.0f);                 // block-uniform

    // Per-thread x-window (skips only provably-zero samples).
    int jx0 = 0, jx1 = 512;
    {
        const float ad = fabsf(dxj);
        if (ad > 1e-9f) {
            const float t0 = (-1.5f  - ixS) / dxj;
            const float t1 = (512.5f - ixS) / dxj;
            const float lo = fminf(t0, t1);
            const float hi = fmaxf(t0, t1);
            jx0 = max(0,   (int)floorf(lo) - 1);
            jx1 = min(512, (int)ceilf(hi) + 2);
        } else if (ixS < -1.5f || ixS > 512.5f) {
            jx0 = 0; jx1 = 0;
        }
    }

    const int c0 = (NCHUNK * blockIdx.y) / NSPLIT;
    const int c1 = (NCHUNK * (blockIdx.y + 1)) / NSPLIT;

    auto stage = [&](int m, __half2* dstbuf) {
        const int R  = m * CH;
        const int nr = min(R + CH, 513) - R;
        const int n16 = nr * (TST / 4);
        const float4* __restrict__ src = (const float4*)(img + R * TST);
        float4* dst = (float4*)dstbuf;
        for (int t = threadIdx.x; t < n16; t += 512)
            cp_async16(&dst[t], &src[t]);
        cp_commit();
    };

    stage(c0, (c0 & 1) ? tbuf1 : tbuf0);

    float acc = 0.0f;

    for (int m = c0; m < c1; m++) {
        if (m + 1 < c1) {
            stage(m + 1, ((m + 1) & 1) ? tbuf1 : tbuf0);
            cp_wait<1>();
        } else {
            cp_wait<0>();
        }
        __syncthreads();

        const int R  = m * CH;
        const int nr = min(R + CH, 513) - R;

        int jlo = first_j_ge((float)(R - 1),      iyS, cy, invcy);
        int jhi = first_j_ge((float)(R + nr - 1), iyS, cy, invcy);
        jlo = max(max(jlo, 0),   jx0);
        jhi = min(min(jhi, 512), jx1);
        const int len = jhi - jlo;

        const float iyl0 = fmaf((float)jlo, cy,  iyS) - (float)(R - 1);
        const float ix0  = fmaf((float)jlo, dxj, ixS) + 2.0f;

        const __half2* __restrict__ tb = (m & 1) ? tbuf1 : tbuf0;

        if (xpos) acc += chunk_accum<true >(tb, len, nr, iyl0, ix0, cy, dxj);
        else      acc += chunk_accum<false>(tb, len, nr, iyl0, ix0, cy, dxj);

        __syncthreads();
    }
    atomicAdd(&g_sino[a * WW + w], acc);
}

// ---------------------------------------------------------------------------
// Kernel 3: MSE (float4, one item per thread) + finalize (last block).
// ---------------------------------------------------------------------------
__global__ __launch_bounds__(256) void loss_kernel(const float* __restrict__ sino_tgt,
                                                   float* __restrict__ out) {
    const int i = blockIdx.x * 256 + threadIdx.x;    // 0..23039, one float4 each
    const float4 s = ((const float4*)g_sino)[i];
    const float4 t = ((const float4*)sino_tgt)[i];
    const float d0 = s.x - t.x, d1 = s.y - t.y, d2 = s.z - t.z, d3 = s.w - t.w;
    float lp = fmaf(d0, d0, fmaf(d1, d1, fmaf(d2, d2, d3 * d3)));

    for (int off = 16; off > 0; off >>= 1)
        lp += __shfl_down_sync(0xFFFFFFFFu, lp, off);
    __shared__ float s_lp[8];
    __shared__ int s_last;
    const int lane = threadIdx.x & 31;
    const int warp = threadIdx.x >> 5;
    if (lane == 0) s_lp[warp] = lp;
    __syncthreads();
    if (threadIdx.x == 0) {
        float tot = 0.0f;
        for (int k = 0; k < 8; k++) tot += s_lp[k];
        atomicAdd(&g_acc0, (double)tot);
        __threadfence();
        const unsigned done = atomicAdd(&g_cnt, 1u);
        s_last = (done == gridDim.x - 1) ? 1 : 0;
    }
    __syncthreads();

    if (s_last) {
        __threadfence();
        double v = (threadIdx.x < TV_BLKS) ? g_tvpart[threadIdx.x] : 0.0;
        for (int off = 16; off > 0; off >>= 1)
            v += __shfl_down_sync(0xFFFFFFFFu, v, off);
        __shared__ double s_d[8];
        if (lane == 0) s_d[warp] = v;
        __syncthreads();
        if (threadIdx.x == 0) {
            double tv = s_d[0] + s_d[1];             // TV_BLKS=64 -> warps 0,1
            const double loss_proj = g_acc0 / (double)(AA * WW);
            const double loss_tv   = tv / (double)((HH - 1) * (WW - 1));
            out[0] = (float)(loss_proj + 0.01 * loss_tv);
        }
    }
}

// ---------------------------------------------------------------------------
extern "C" void kernel_launch(void* const* d_in, const int* in_sizes, int n_in,
                              void* d_out, int out_size) {
    const float* pred     = (const float*)d_in[0];   // [1,512,512]
    const float* sinogram = (const float*)d_in[1];   // [1,180,512]
    const float* angles   = (const float*)d_in[2];   // [180]
    float* out = (float*)d_out;

    cudaFuncSetAttribute(radon_kernel,
                         cudaFuncAttributeMaxDynamicSharedMemorySize, DYN_SMEM);

    prep_kernel<<<PREP_BLKS, 544>>>(pred);

    dim3 rgrid(AA, NSPLIT);                          // 180 x 10 = 1800 blocks
    radon_kernel<<<rgrid, 512, DYN_SMEM>>>(angles);

    loss_kernel<<<MSE_BLKS, 256>>>(sinogram, out);
}